// round 1
// baseline (speedup 1.0000x reference)
#include <cuda_runtime.h>

// Problem dims (fixed by dataset)
constexpr int Bb = 4;      // batch
constexpr int Nq = 4096;   // H*W
constexpr int C  = 256;    // channels
constexpr int CK = 32;     // key/query channels

// Scratch in __device__ globals (allocation-free rule)
__device__ float g_f[(size_t)Bb * Nq * CK];              // keys
__device__ float g_g[(size_t)Bb * Nq * CK];              // queries
__device__ float g_h[(size_t)Bb * Nq * C];               // values
__device__ float g_s[(size_t)Bb * Nq * Nq];              // scores / probs (256 MB)

// ---------------------------------------------------------------------------
// Kernel 1: f = x@Wf + bf, g = x@Wg + bg   (K=256, Nout=32 each)
// Block: 32 rows of x, 256 threads. Each thread owns 1 out col x 4 rows.
// ---------------------------------------------------------------------------
__global__ void fg_kernel(const float* __restrict__ x,
                          const float* __restrict__ Wf, const float* __restrict__ bfv,
                          const float* __restrict__ Wg, const float* __restrict__ bgv) {
    __shared__ float xs[32][260];
    const int t = threadIdx.x;
    const int rowbase = blockIdx.x * 32;

    for (int i = t; i < 32 * (C / 4); i += 256) {
        int r = i / (C / 4), c4 = i % (C / 4);
        float4 v = *(const float4*)(x + (size_t)(rowbase + r) * C + c4 * 4);
        *(float4*)&xs[r][c4 * 4] = v;
    }
    __syncthreads();

    const int c = t & 31, rg = t >> 5;
    float af[4] = {0.f, 0.f, 0.f, 0.f};
    float ag[4] = {0.f, 0.f, 0.f, 0.f};
    #pragma unroll 4
    for (int k = 0; k < C; k++) {
        float wf = Wf[k * CK + c];
        float wg = Wg[k * CK + c];
        #pragma unroll
        for (int r4 = 0; r4 < 4; r4++) {
            float xv = xs[rg + r4 * 8][k];
            af[r4] += xv * wf;
            ag[r4] += xv * wg;
        }
    }
    #pragma unroll
    for (int r4 = 0; r4 < 4; r4++) {
        size_t o = (size_t)(rowbase + rg + r4 * 8) * CK + c;
        g_f[o] = af[r4] + bfv[c];
        g_g[o] = ag[r4] + bgv[c];
    }
}

// ---------------------------------------------------------------------------
// Kernel 2/5: generic row-major GEMM  Cout[M,256] = A[M,K] @ B[K,256]
//   EPI=false: + bias[col]          (h projection, writes g_h)
//   EPI=true : gamma*acc + resid    (PV output, writes y = d_out)
// 128x128 tile, BK=16, 256 threads, 8x8 microtile (2x2 of 4x4 -> conflict-free
// LDS.128 fragments), single-stage register prefetch.
// ---------------------------------------------------------------------------
template <bool EPI>
__global__ __launch_bounds__(256, 2)
void gemm_kernel(const float* __restrict__ A, const float* __restrict__ Bm,
                 const float* __restrict__ bias, const float* __restrict__ resid,
                 const float* __restrict__ gamma_p, float* __restrict__ Cout,
                 int K, size_t strideA, size_t strideB, size_t strideC) {
    __shared__ float As[16][128];   // transposed: As[k][m]
    __shared__ float Bs[16][128];   // natural:    Bs[k][n]

    const int t = threadIdx.x;
    const int mbase = blockIdx.y * 128, nbase = blockIdx.x * 128;
    const float* Ab = A + (size_t)blockIdx.z * strideA;
    const float* Bp = Bm + (size_t)blockIdx.z * strideB;
    const size_t coff = (size_t)blockIdx.z * strideC;

    // A tile loader: 128x16 = 512 float4, 2 per thread
    const int ar0 = t >> 2, ar1 = (t >> 2) + 64;
    const int ac  = (t & 3) * 4;
    // B tile loader: 16x128 = 512 float4, 2 per thread
    const int br0 = t >> 5, br1 = (t >> 5) + 8;
    const int bc  = (t & 31) * 4;

    float4 pa0, pa1, pb0, pb1;
    pa0 = *(const float4*)(Ab + (size_t)(mbase + ar0) * K + ac);
    pa1 = *(const float4*)(Ab + (size_t)(mbase + ar1) * K + ac);
    pb0 = *(const float4*)(Bp + (size_t)br0 * C + nbase + bc);
    pb1 = *(const float4*)(Bp + (size_t)br1 * C + nbase + bc);

    float acc[8][8] = {};
    const int tx = t & 15, ty = t >> 4;
    const int ntiles = K >> 4;

    for (int tile = 0; tile < ntiles; tile++) {
        __syncthreads();
        As[ac + 0][ar0] = pa0.x; As[ac + 1][ar0] = pa0.y;
        As[ac + 2][ar0] = pa0.z; As[ac + 3][ar0] = pa0.w;
        As[ac + 0][ar1] = pa1.x; As[ac + 1][ar1] = pa1.y;
        As[ac + 2][ar1] = pa1.z; As[ac + 3][ar1] = pa1.w;
        *(float4*)&Bs[br0][bc] = pb0;
        *(float4*)&Bs[br1][bc] = pb1;
        __syncthreads();

        if (tile + 1 < ntiles) {
            int k0 = (tile + 1) << 4;
            pa0 = *(const float4*)(Ab + (size_t)(mbase + ar0) * K + k0 + ac);
            pa1 = *(const float4*)(Ab + (size_t)(mbase + ar1) * K + k0 + ac);
            pb0 = *(const float4*)(Bp + (size_t)(k0 + br0) * C + nbase + bc);
            pb1 = *(const float4*)(Bp + (size_t)(k0 + br1) * C + nbase + bc);
        }

        #pragma unroll
        for (int k = 0; k < 16; k++) {
            float a[8], b[8];
            *(float4*)&a[0] = *(const float4*)&As[k][ty * 4];
            *(float4*)&a[4] = *(const float4*)&As[k][64 + ty * 4];
            *(float4*)&b[0] = *(const float4*)&Bs[k][tx * 4];
            *(float4*)&b[4] = *(const float4*)&Bs[k][64 + tx * 4];
            #pragma unroll
            for (int i = 0; i < 8; i++)
                #pragma unroll
                for (int j = 0; j < 8; j++)
                    acc[i][j] += a[i] * b[j];
        }
    }

    float gam = 0.f;
    if (EPI) gam = *gamma_p;
    #pragma unroll
    for (int i = 0; i < 8; i++) {
        int gr = mbase + (i < 4 ? ty * 4 + i : 64 + ty * 4 + i - 4);
        size_t rowo = coff + (size_t)gr * C;
        #pragma unroll
        for (int jh = 0; jh < 2; jh++) {
            int gc = nbase + (jh == 0 ? tx * 4 : 64 + tx * 4);
            float4 o;
            if (EPI) {
                float4 rx = *(const float4*)(resid + rowo + gc);
                o.x = gam * acc[i][jh * 4 + 0] + rx.x;
                o.y = gam * acc[i][jh * 4 + 1] + rx.y;
                o.z = gam * acc[i][jh * 4 + 2] + rx.z;
                o.w = gam * acc[i][jh * 4 + 3] + rx.w;
            } else {
                o.x = acc[i][jh * 4 + 0] + bias[gc + 0];
                o.y = acc[i][jh * 4 + 1] + bias[gc + 1];
                o.z = acc[i][jh * 4 + 2] + bias[gc + 2];
                o.w = acc[i][jh * 4 + 3] + bias[gc + 3];
            }
            *(float4*)(Cout + rowo + gc) = o;
        }
    }
}

// ---------------------------------------------------------------------------
// Kernel 3: scores  s[b,q,n] = sum_k g[b,q,k] * f[b,n,k]   (K=32, one shot)
// ---------------------------------------------------------------------------
__global__ __launch_bounds__(256, 2)
void score_kernel() {
    __shared__ float Gs[CK][128];
    __shared__ float Fs[CK][128];
    const int t = threadIdx.x;
    const int mbase = blockIdx.y * 128, nbase = blockIdx.x * 128;
    const size_t zoff = (size_t)blockIdx.z * Nq * CK;

    #pragma unroll
    for (int i = 0; i < 4; i++) {
        int idx = t + i * 256;
        int r = idx >> 3, c4 = idx & 7;
        float4 v = *(const float4*)(g_g + zoff + (size_t)(mbase + r) * CK + c4 * 4);
        Gs[c4 * 4 + 0][r] = v.x; Gs[c4 * 4 + 1][r] = v.y;
        Gs[c4 * 4 + 2][r] = v.z; Gs[c4 * 4 + 3][r] = v.w;
        float4 w = *(const float4*)(g_f + zoff + (size_t)(nbase + r) * CK + c4 * 4);
        Fs[c4 * 4 + 0][r] = w.x; Fs[c4 * 4 + 1][r] = w.y;
        Fs[c4 * 4 + 2][r] = w.z; Fs[c4 * 4 + 3][r] = w.w;
    }
    __syncthreads();

    const int tx = t & 15, ty = t >> 4;
    float acc[8][8] = {};
    #pragma unroll
    for (int k = 0; k < CK; k++) {
        float a[8], b[8];
        *(float4*)&a[0] = *(const float4*)&Gs[k][ty * 4];
        *(float4*)&a[4] = *(const float4*)&Gs[k][64 + ty * 4];
        *(float4*)&b[0] = *(const float4*)&Fs[k][tx * 4];
        *(float4*)&b[4] = *(const float4*)&Fs[k][64 + tx * 4];
        #pragma unroll
        for (int i = 0; i < 8; i++)
            #pragma unroll
            for (int j = 0; j < 8; j++)
                acc[i][j] += a[i] * b[j];
    }

    float* sout = g_s + (size_t)blockIdx.z * Nq * Nq;
    #pragma unroll
    for (int i = 0; i < 8; i++) {
        int gr = mbase + (i < 4 ? ty * 4 + i : 64 + ty * 4 + i - 4);
        #pragma unroll
        for (int jh = 0; jh < 2; jh++) {
            int gc = nbase + (jh == 0 ? tx * 4 : 64 + tx * 4);
            float4 o;
            o.x = acc[i][jh * 4 + 0]; o.y = acc[i][jh * 4 + 1];
            o.z = acc[i][jh * 4 + 2]; o.w = acc[i][jh * 4 + 3];
            *(float4*)(sout + (size_t)gr * Nq + gc) = o;
        }
    }
}

// ---------------------------------------------------------------------------
// Kernel 4: row softmax over N=4096, in place on g_s. One block per row.
// ---------------------------------------------------------------------------
__global__ void softmax_kernel() {
    float4* row = (float4*)(g_s + (size_t)blockIdx.x * Nq);
    const int t = threadIdx.x;
    __shared__ float red[8];

    float4 v[4];
    float mx = -3.4e38f;
    #pragma unroll
    for (int i = 0; i < 4; i++) {
        v[i] = row[t + i * 256];
        mx = fmaxf(mx, fmaxf(fmaxf(v[i].x, v[i].y), fmaxf(v[i].z, v[i].w)));
    }
    #pragma unroll
    for (int o = 16; o > 0; o >>= 1) mx = fmaxf(mx, __shfl_xor_sync(0xffffffffu, mx, o));
    if ((t & 31) == 0) red[t >> 5] = mx;
    __syncthreads();
    mx = red[0];
    #pragma unroll
    for (int i = 1; i < 8; i++) mx = fmaxf(mx, red[i]);

    float sum = 0.f;
    #pragma unroll
    for (int i = 0; i < 4; i++) {
        v[i].x = __expf(v[i].x - mx);
        v[i].y = __expf(v[i].y - mx);
        v[i].z = __expf(v[i].z - mx);
        v[i].w = __expf(v[i].w - mx);
        sum += v[i].x + v[i].y + v[i].z + v[i].w;
    }
    __syncthreads();   // red reuse
    #pragma unroll
    for (int o = 16; o > 0; o >>= 1) sum += __shfl_xor_sync(0xffffffffu, sum, o);
    if ((t & 31) == 0) red[t >> 5] = sum;
    __syncthreads();
    sum = red[0];
    #pragma unroll
    for (int i = 1; i < 8; i++) sum += red[i];

    float inv = 1.f / sum;
    #pragma unroll
    for (int i = 0; i < 4; i++) {
        v[i].x *= inv; v[i].y *= inv; v[i].z *= inv; v[i].w *= inv;
        row[t + i * 256] = v[i];
    }
}

// ---------------------------------------------------------------------------
extern "C" void kernel_launch(void* const* d_in, const int* in_sizes, int n_in,
                              void* d_out, int out_size) {
    (void)in_sizes; (void)n_in; (void)out_size;
    const float* x     = (const float*)d_in[0];
    const float* Wf    = (const float*)d_in[1];
    const float* bf    = (const float*)d_in[2];
    const float* Wg    = (const float*)d_in[3];
    const float* bg    = (const float*)d_in[4];
    const float* Wh    = (const float*)d_in[5];
    const float* bh    = (const float*)d_in[6];
    const float* gamma = (const float*)d_in[7];
    float* y = (float*)d_out;

    void *ph = nullptr, *ps = nullptr;
    cudaGetSymbolAddress(&ph, g_h);
    cudaGetSymbolAddress(&ps, g_s);

    // 1) keys/queries
    fg_kernel<<<(Bb * Nq) / 32, 256>>>(x, Wf, bf, Wg, bg);
    // 2) values: h = x @ Wh + bh   (M=16384, K=256)
    gemm_kernel<false><<<dim3(2, (Bb * Nq) / 128, 1), 256>>>(
        x, Wh, bh, nullptr, nullptr, (float*)ph, C, 0, 0, 0);
    // 3) scores
    score_kernel<<<dim3(Nq / 128, Nq / 128, Bb), 256>>>();
    // 4) softmax
    softmax_kernel<<<Bb * Nq, 256>>>();
    // 5) o = P @ h ; y = gamma*o + x   (per-batch, K=4096)
    gemm_kernel<true><<<dim3(2, Nq / 128, Bb), 256>>>(
        (const float*)ps, (const float*)ph, nullptr, x, gamma, y,
        Nq, (size_t)Nq * Nq, (size_t)Nq * C, (size_t)Nq * C);
}

// round 3
// speedup vs baseline: 1.8256x; 1.8256x over previous
#include <cuda_runtime.h>
#include <cstdint>

// Problem dims (fixed by dataset)
constexpr int Bb = 4;      // batch
constexpr int Nq = 4096;   // H*W
constexpr int C  = 256;    // channels
constexpr int CK = 32;     // key/query channels

// Scratch in __device__ globals (allocation-free rule)
__device__ float g_f[(size_t)Bb * Nq * CK];              // keys
__device__ float g_g[(size_t)Bb * Nq * CK];              // queries
__device__ float g_hT[(size_t)Bb * C * Nq];              // values, TRANSPOSED [b][c][n]
__device__ float g_s[(size_t)Bb * Nq * Nq];              // scores / probs (256 MB)

__device__ __forceinline__ uint32_t smem_u32(const void* p) {
    return (uint32_t)__cvta_generic_to_shared(p);
}
__device__ __forceinline__ void cp16(uint32_t s, const void* g) {
    asm volatile("cp.async.cg.shared.global [%0], [%1], 16;" :: "r"(s), "l"(g));
}
__device__ __forceinline__ void cp_commit() {
    asm volatile("cp.async.commit_group;" ::: "memory");
}
__device__ __forceinline__ uint32_t f2tf32(float f) {
    uint32_t u;
    asm("cvt.rna.tf32.f32 %0, %1;" : "=r"(u) : "f"(f));
    return u;
}
__device__ __forceinline__ void mma_tf32(float* d, const uint32_t* a, const uint32_t* bfr) {
    asm volatile(
        "mma.sync.aligned.m16n8k8.row.col.f32.tf32.tf32.f32 "
        "{%0,%1,%2,%3}, {%4,%5,%6,%7}, {%8,%9}, {%0,%1,%2,%3};"
        : "+f"(d[0]), "+f"(d[1]), "+f"(d[2]), "+f"(d[3])
        : "r"(a[0]), "r"(a[1]), "r"(a[2]), "r"(a[3]), "r"(bfr[0]), "r"(bfr[1]));
}

// ===========================================================================
// Kernel 1: f = x@Wf + bf, g = x@Wg + bg   (K=256, Nout=32 each)
// ===========================================================================
__global__ void fg_kernel(const float* __restrict__ x,
                          const float* __restrict__ Wf, const float* __restrict__ bfv,
                          const float* __restrict__ Wg, const float* __restrict__ bgv) {
    __shared__ float xs[32][260];
    const int t = threadIdx.x;
    const int rowbase = blockIdx.x * 32;

    for (int i = t; i < 32 * (C / 4); i += 256) {
        int r = i / (C / 4), c4 = i % (C / 4);
        float4 v = *(const float4*)(x + (size_t)(rowbase + r) * C + c4 * 4);
        *(float4*)&xs[r][c4 * 4] = v;
    }
    __syncthreads();

    const int c = t & 31, rg = t >> 5;
    float af[4] = {0.f, 0.f, 0.f, 0.f};
    float ag[4] = {0.f, 0.f, 0.f, 0.f};
    #pragma unroll 4
    for (int k = 0; k < C; k++) {
        float wf = Wf[k * CK + c];
        float wg = Wg[k * CK + c];
        #pragma unroll
        for (int r4 = 0; r4 < 4; r4++) {
            float xv = xs[rg + r4 * 8][k];
            af[r4] += xv * wf;
            ag[r4] += xv * wg;
        }
    }
    #pragma unroll
    for (int r4 = 0; r4 < 4; r4++) {
        size_t o = (size_t)(rowbase + rg + r4 * 8) * CK + c;
        g_f[o] = af[r4] + bfv[c];
        g_g[o] = ag[r4] + bgv[c];
    }
}

// ===========================================================================
// Kernel 2: h projection, writes TRANSPOSED  g_hT[b][c][n] = (x@Wh + bh)^T
// ===========================================================================
__global__ __launch_bounds__(256, 2)
void gemmh_kernel(const float* __restrict__ A, const float* __restrict__ Bm,
                  const float* __restrict__ bias) {
    __shared__ float As[16][128];
    __shared__ float Bs[16][128];

    const int t = threadIdx.x;
    const int mbase = blockIdx.y * 128, nbase = blockIdx.x * 128;

    const int ar0 = t >> 2, ar1 = (t >> 2) + 64;
    const int ac  = (t & 3) * 4;
    const int br0 = t >> 5, br1 = (t >> 5) + 8;
    const int bc  = (t & 31) * 4;

    float4 pa0, pa1, pb0, pb1;
    pa0 = *(const float4*)(A + (size_t)(mbase + ar0) * C + ac);
    pa1 = *(const float4*)(A + (size_t)(mbase + ar1) * C + ac);
    pb0 = *(const float4*)(Bm + (size_t)br0 * C + nbase + bc);
    pb1 = *(const float4*)(Bm + (size_t)br1 * C + nbase + bc);

    float acc[8][8] = {};
    const int tx = t & 15, ty = t >> 4;
    const int ntiles = C >> 4;

    for (int tile = 0; tile < ntiles; tile++) {
        __syncthreads();
        As[ac + 0][ar0] = pa0.x; As[ac + 1][ar0] = pa0.y;
        As[ac + 2][ar0] = pa0.z; As[ac + 3][ar0] = pa0.w;
        As[ac + 0][ar1] = pa1.x; As[ac + 1][ar1] = pa1.y;
        As[ac + 2][ar1] = pa1.z; As[ac + 3][ar1] = pa1.w;
        *(float4*)&Bs[br0][bc] = pb0;
        *(float4*)&Bs[br1][bc] = pb1;
        __syncthreads();

        if (tile + 1 < ntiles) {
            int k0 = (tile + 1) << 4;
            pa0 = *(const float4*)(A + (size_t)(mbase + ar0) * C + k0 + ac);
            pa1 = *(const float4*)(A + (size_t)(mbase + ar1) * C + k0 + ac);
            pb0 = *(const float4*)(Bm + (size_t)(k0 + br0) * C + nbase + bc);
            pb1 = *(const float4*)(Bm + (size_t)(k0 + br1) * C + nbase + bc);
        }

        #pragma unroll
        for (int k = 0; k < 16; k++) {
            float a[8], b[8];
            *(float4*)&a[0] = *(const float4*)&As[k][ty * 4];
            *(float4*)&a[4] = *(const float4*)&As[k][64 + ty * 4];
            *(float4*)&b[0] = *(const float4*)&Bs[k][tx * 4];
            *(float4*)&b[4] = *(const float4*)&Bs[k][64 + tx * 4];
            #pragma unroll
            for (int i = 0; i < 8; i++)
                #pragma unroll
                for (int j = 0; j < 8; j++)
                    acc[i][j] += a[i] * b[j];
        }
    }

    // transposed epilogue: hT[b][channel][token]
    #pragma unroll
    for (int j = 0; j < 8; j++) {
        int gc = nbase + (j < 4 ? tx * 4 + j : 64 + tx * 4 + (j - 4));
        float bi = bias[gc];
        int gr0 = mbase + ty * 4;
        int bb0 = gr0 >> 12, n0 = gr0 & 4095;
        float4 v0;
        v0.x = acc[0][j] + bi; v0.y = acc[1][j] + bi;
        v0.z = acc[2][j] + bi; v0.w = acc[3][j] + bi;
        *(float4*)(g_hT + ((size_t)bb0 * C + gc) * Nq + n0) = v0;
        int gr1 = mbase + 64 + ty * 4;
        int bb1 = gr1 >> 12, n1 = gr1 & 4095;
        float4 v1;
        v1.x = acc[4][j] + bi; v1.y = acc[5][j] + bi;
        v1.z = acc[6][j] + bi; v1.w = acc[7][j] + bi;
        *(float4*)(g_hT + ((size_t)bb1 * C + gc) * Nq + n1) = v1;
    }
}

// ===========================================================================
// Kernel 3: scores  s[b,q,n] = sum_k g[b,q,k] * f[b,n,k]   (K=32, fp32)
// ===========================================================================
__global__ __launch_bounds__(256, 2)
void score_kernel() {
    __shared__ float Gs[CK][128];
    __shared__ float Fs[CK][128];
    const int t = threadIdx.x;
    const int mbase = blockIdx.y * 128, nbase = blockIdx.x * 128;
    const size_t zoff = (size_t)blockIdx.z * Nq * CK;

    #pragma unroll
    for (int i = 0; i < 4; i++) {
        int idx = t + i * 256;
        int r = idx >> 3, c4 = idx & 7;
        float4 v = *(const float4*)(g_g + zoff + (size_t)(mbase + r) * CK + c4 * 4);
        Gs[c4 * 4 + 0][r] = v.x; Gs[c4 * 4 + 1][r] = v.y;
        Gs[c4 * 4 + 2][r] = v.z; Gs[c4 * 4 + 3][r] = v.w;
        float4 w = *(const float4*)(g_f + zoff + (size_t)(nbase + r) * CK + c4 * 4);
        Fs[c4 * 4 + 0][r] = w.x; Fs[c4 * 4 + 1][r] = w.y;
        Fs[c4 * 4 + 2][r] = w.z; Fs[c4 * 4 + 3][r] = w.w;
    }
    __syncthreads();

    const int tx = t & 15, ty = t >> 4;
    float acc[8][8] = {};
    #pragma unroll
    for (int k = 0; k < CK; k++) {
        float a[8], b[8];
        *(float4*)&a[0] = *(const float4*)&Gs[k][ty * 4];
        *(float4*)&a[4] = *(const float4*)&Gs[k][64 + ty * 4];
        *(float4*)&b[0] = *(const float4*)&Fs[k][tx * 4];
        *(float4*)&b[4] = *(const float4*)&Fs[k][64 + tx * 4];
        #pragma unroll
        for (int i = 0; i < 8; i++)
            #pragma unroll
            for (int j = 0; j < 8; j++)
                acc[i][j] += a[i] * b[j];
    }

    float* sout = g_s + (size_t)blockIdx.z * Nq * Nq;
    #pragma unroll
    for (int i = 0; i < 8; i++) {
        int gr = mbase + (i < 4 ? ty * 4 + i : 64 + ty * 4 + i - 4);
        #pragma unroll
        for (int jh = 0; jh < 2; jh++) {
            int gc = nbase + (jh == 0 ? tx * 4 : 64 + tx * 4);
            float4 o;
            o.x = acc[i][jh * 4 + 0]; o.y = acc[i][jh * 4 + 1];
            o.z = acc[i][jh * 4 + 2]; o.w = acc[i][jh * 4 + 3];
            *(float4*)(sout + (size_t)gr * Nq + gc) = o;
        }
    }
}

// ===========================================================================
// Kernel 4: row softmax over N=4096, in place on g_s.
// ===========================================================================
__global__ void softmax_kernel() {
    float4* row = (float4*)(g_s + (size_t)blockIdx.x * Nq);
    const int t = threadIdx.x;
    __shared__ float red[8];

    float4 v[4];
    float mx = -3.4e38f;
    #pragma unroll
    for (int i = 0; i < 4; i++) {
        v[i] = row[t + i * 256];
        mx = fmaxf(mx, fmaxf(fmaxf(v[i].x, v[i].y), fmaxf(v[i].z, v[i].w)));
    }
    #pragma unroll
    for (int o = 16; o > 0; o >>= 1) mx = fmaxf(mx, __shfl_xor_sync(0xffffffffu, mx, o));
    if ((t & 31) == 0) red[t >> 5] = mx;
    __syncthreads();
    mx = red[0];
    #pragma unroll
    for (int i = 1; i < 8; i++) mx = fmaxf(mx, red[i]);

    float sum = 0.f;
    #pragma unroll
    for (int i = 0; i < 4; i++) {
        v[i].x = __expf(v[i].x - mx);
        v[i].y = __expf(v[i].y - mx);
        v[i].z = __expf(v[i].z - mx);
        v[i].w = __expf(v[i].w - mx);
        sum += v[i].x + v[i].y + v[i].z + v[i].w;
    }
    __syncthreads();
    #pragma unroll
    for (int o = 16; o > 0; o >>= 1) sum += __shfl_xor_sync(0xffffffffu, sum, o);
    if ((t & 31) == 0) red[t >> 5] = sum;
    __syncthreads();
    sum = red[0];
    #pragma unroll
    for (int i = 1; i < 8; i++) sum += red[i];

    float inv = 1.f / sum;
    #pragma unroll
    for (int i = 0; i < 4; i++) {
        v[i].x *= inv; v[i].y *= inv; v[i].z *= inv; v[i].w *= inv;
        row[t + i * 256] = v[i];
    }
}

// ===========================================================================
// Kernel 5: PV with warp-level tf32 mma.sync (HMMA).
//   o[q,c] = sum_n P[q,n] * hT[c,n] ; y = gamma*o + x
//   CTA 128(M=q) x 128(N=c), BK=32, 8 warps (2x4), warp tile 64x32.
//   2-stage cp.async double buffer. Smem tiles [row][36] (pad 4) so fragment
//   loads are bank-conflict-free (bank = 4*(lane>>2)+(lane&3)).
// ===========================================================================
constexpr int PV_ROWSZ  = 36;                        // 32 + 4 pad floats
constexpr int PV_TILE_F = 128 * PV_ROWSZ;            // floats per tile
constexpr int PV_SMEM   = 2 * 2 * PV_TILE_F * 4;     // 73728 B

__global__ __launch_bounds__(256, 1)
void pv_kernel(const float* __restrict__ gamma_p,
               const float* __restrict__ x, float* __restrict__ y) {
    extern __shared__ float sm[];
    float* Abuf = sm;                    // [2][128][36]
    float* Bbuf = sm + 2 * PV_TILE_F;    // [2][128][36]

    const int t = threadIdx.x;
    const int lane = t & 31, wid = t >> 5;
    const int wm = wid >> 2, wn = wid & 3;       // warp grid 2(M) x 4(N)
    const int nbase = blockIdx.x * 128;
    const int qbase = blockIdx.y * 128;
    const int b = blockIdx.z;
    const float* Pm  = g_s  + (size_t)b * Nq * Nq;
    const float* hTb = g_hT + (size_t)b * C * Nq;

    // loader thread mapping: idx -> row (0..127), 16B chunk c4 (0..7)
    const int lr = (t * 4 + 0) >> 5;   // unused helper removed below
    (void)lr;

    auto load_stage = [&](int chunk) {
        int st = chunk & 1;
        int k0 = chunk * 32;
        float* Ad = Abuf + st * PV_TILE_F;
        float* Bd = Bbuf + st * PV_TILE_F;
        #pragma unroll
        for (int i = 0; i < 4; i++) {
            int idx = t + i * 256;
            int r = idx >> 3, c4 = idx & 7;
            cp16(smem_u32(Ad + r * PV_ROWSZ + c4 * 4),
                 Pm + (size_t)(qbase + r) * Nq + k0 + c4 * 4);
            cp16(smem_u32(Bd + r * PV_ROWSZ + c4 * 4),
                 hTb + (size_t)(nbase + r) * Nq + k0 + c4 * 4);
        }
        cp_commit();
    };

    float acc[4][4][4] = {};   // [mtile][ntile][reg]

    load_stage(0);

    const int NCH = Nq / 32;   // 128
    for (int c = 0; c < NCH; c++) {
        if (c + 1 < NCH) {
            load_stage(c + 1);
            asm volatile("cp.async.wait_group 1;" ::: "memory");
        } else {
            asm volatile("cp.async.wait_group 0;" ::: "memory");
        }
        __syncthreads();

        const float* Asb = Abuf + (c & 1) * PV_TILE_F;
        const float* Bsb = Bbuf + (c & 1) * PV_TILE_F;

        #pragma unroll
        for (int ks = 0; ks < 4; ks++) {
            uint32_t afrag[4][4];
            #pragma unroll
            for (int mt = 0; mt < 4; mt++) {
                int r0 = (wm * 64 + mt * 16 + (lane >> 2)) * PV_ROWSZ;
                int cc = ks * 8 + (lane & 3);
                afrag[mt][0] = f2tf32(Asb[r0 + cc]);
                afrag[mt][1] = f2tf32(Asb[r0 + 8 * PV_ROWSZ + cc]);
                afrag[mt][2] = f2tf32(Asb[r0 + cc + 4]);
                afrag[mt][3] = f2tf32(Asb[r0 + 8 * PV_ROWSZ + cc + 4]);
            }
            uint32_t bfrag[4][2];
            #pragma unroll
            for (int nt = 0; nt < 4; nt++) {
                int rn = (wn * 32 + nt * 8 + (lane >> 2)) * PV_ROWSZ;
                int cc = ks * 8 + (lane & 3);
                bfrag[nt][0] = f2tf32(Bsb[rn + cc]);
                bfrag[nt][1] = f2tf32(Bsb[rn + cc + 4]);
            }
            #pragma unroll
            for (int mt = 0; mt < 4; mt++)
                #pragma unroll
                for (int nt = 0; nt < 4; nt++)
                    mma_tf32(acc[mt][nt], afrag[mt], bfrag[nt]);
        }
        __syncthreads();
    }

    // epilogue: y = gamma*o + x
    const float gam = __ldg(gamma_p);
    #pragma unroll
    for (int mt = 0; mt < 4; mt++) {
        #pragma unroll
        for (int nt = 0; nt < 4; nt++) {
            int row = qbase + wm * 64 + mt * 16 + (lane >> 2);
            int col = nbase + wn * 32 + nt * 8 + 2 * (lane & 3);
            size_t base = ((size_t)b * Nq + row) * C + col;
            float2 x0 = *(const float2*)(x + base);
            float2 o0;
            o0.x = gam * acc[mt][nt][0] + x0.x;
            o0.y = gam * acc[mt][nt][1] + x0.y;
            *(float2*)(y + base) = o0;
            size_t base2 = base + 8 * C;
            float2 x1 = *(const float2*)(x + base2);
            float2 o1;
            o1.x = gam * acc[mt][nt][2] + x1.x;
            o1.y = gam * acc[mt][nt][3] + x1.y;
            *(float2*)(y + base2) = o1;
        }
    }
}

// ===========================================================================
extern "C" void kernel_launch(void* const* d_in, const int* in_sizes, int n_in,
                              void* d_out, int out_size) {
    (void)in_sizes; (void)n_in; (void)out_size;
    const float* x     = (const float*)d_in[0];
    const float* Wf    = (const float*)d_in[1];
    const float* bf    = (const float*)d_in[2];
    const float* Wg    = (const float*)d_in[3];
    const float* bg    = (const float*)d_in[4];
    const float* Wh    = (const float*)d_in[5];
    const float* bh    = (const float*)d_in[6];
    const float* gamma = (const float*)d_in[7];
    float* y = (float*)d_out;

    cudaFuncSetAttribute(pv_kernel, cudaFuncAttributeMaxDynamicSharedMemorySize, PV_SMEM);

    fg_kernel<<<(Bb * Nq) / 32, 256>>>(x, Wf, bf, Wg, bg);
    gemmh_kernel<<<dim3(2, (Bb * Nq) / 128), 256>>>(x, Wh, bh);
    score_kernel<<<dim3(Nq / 128, Nq / 128, Bb), 256>>>();
    softmax_kernel<<<Bb * Nq, 256>>>();
    pv_kernel<<<dim3(2, Nq / 128, Bb), 256, PV_SMEM>>>(gamma, x, y);
}

// round 4
// speedup vs baseline: 2.1739x; 1.1908x over previous
#include <cuda_runtime.h>
#include <cstdint>

// Problem dims (fixed by dataset)
constexpr int Bb = 4;      // batch
constexpr int Nq = 4096;   // H*W
constexpr int C  = 256;    // channels
constexpr int CK = 32;     // key/query channels

// Scratch in __device__ globals (allocation-free rule)
__device__ float g_f[(size_t)Bb * Nq * CK];              // keys
__device__ float g_g[(size_t)Bb * Nq * CK];              // queries
__device__ float g_hT[(size_t)Bb * C * Nq];              // values, TRANSPOSED [b][c][n]
__device__ float g_s[(size_t)Bb * Nq * Nq];              // raw scores (256 MB)

__device__ __forceinline__ uint32_t smem_u32(const void* p) {
    return (uint32_t)__cvta_generic_to_shared(p);
}
__device__ __forceinline__ void cp16(uint32_t s, const void* g) {
    asm volatile("cp.async.cg.shared.global [%0], [%1], 16;" :: "r"(s), "l"(g));
}
__device__ __forceinline__ void cp_commit() {
    asm volatile("cp.async.commit_group;" ::: "memory");
}
__device__ __forceinline__ uint32_t f2tf32(float f) {
    uint32_t u;
    asm("cvt.rna.tf32.f32 %0, %1;" : "=r"(u) : "f"(f));
    return u;
}
__device__ __forceinline__ void mma_tf32(float* d, const uint32_t* a, const uint32_t* bfr) {
    asm volatile(
        "mma.sync.aligned.m16n8k8.row.col.f32.tf32.tf32.f32 "
        "{%0,%1,%2,%3}, {%4,%5,%6,%7}, {%8,%9}, {%0,%1,%2,%3};"
        : "+f"(d[0]), "+f"(d[1]), "+f"(d[2]), "+f"(d[3])
        : "r"(a[0]), "r"(a[1]), "r"(a[2]), "r"(a[3]), "r"(bfr[0]), "r"(bfr[1]));
}

// ===========================================================================
// Kernel 1: f = x@Wf + bf, g = x@Wg + bg   (K=256, Nout=32 each)
// ===========================================================================
__global__ void fg_kernel(const float* __restrict__ x,
                          const float* __restrict__ Wf, const float* __restrict__ bfv,
                          const float* __restrict__ Wg, const float* __restrict__ bgv) {
    __shared__ float xs[32][260];
    const int t = threadIdx.x;
    const int rowbase = blockIdx.x * 32;

    for (int i = t; i < 32 * (C / 4); i += 256) {
        int r = i / (C / 4), c4 = i % (C / 4);
        float4 v = *(const float4*)(x + (size_t)(rowbase + r) * C + c4 * 4);
        *(float4*)&xs[r][c4 * 4] = v;
    }
    __syncthreads();

    const int c = t & 31, rg = t >> 5;
    float af[4] = {0.f, 0.f, 0.f, 0.f};
    float ag[4] = {0.f, 0.f, 0.f, 0.f};
    #pragma unroll 4
    for (int k = 0; k < C; k++) {
        float wf = Wf[k * CK + c];
        float wg = Wg[k * CK + c];
        #pragma unroll
        for (int r4 = 0; r4 < 4; r4++) {
            float xv = xs[rg + r4 * 8][k];
            af[r4] += xv * wf;
            ag[r4] += xv * wg;
        }
    }
    #pragma unroll
    for (int r4 = 0; r4 < 4; r4++) {
        size_t o = (size_t)(rowbase + rg + r4 * 8) * CK + c;
        g_f[o] = af[r4] + bfv[c];
        g_g[o] = ag[r4] + bgv[c];
    }
}

// ===========================================================================
// Kernel 2: h projection, writes TRANSPOSED  g_hT[b][c][n] = (x@Wh + bh)^T
// ===========================================================================
__global__ __launch_bounds__(256, 2)
void gemmh_kernel(const float* __restrict__ A, const float* __restrict__ Bm,
                  const float* __restrict__ bias) {
    __shared__ float As[16][128];
    __shared__ float Bs[16][128];

    const int t = threadIdx.x;
    const int mbase = blockIdx.y * 128, nbase = blockIdx.x * 128;

    const int ar0 = t >> 2, ar1 = (t >> 2) + 64;
    const int ac  = (t & 3) * 4;
    const int br0 = t >> 5, br1 = (t >> 5) + 8;
    const int bc  = (t & 31) * 4;

    float4 pa0, pa1, pb0, pb1;
    pa0 = *(const float4*)(A + (size_t)(mbase + ar0) * C + ac);
    pa1 = *(const float4*)(A + (size_t)(mbase + ar1) * C + ac);
    pb0 = *(const float4*)(Bm + (size_t)br0 * C + nbase + bc);
    pb1 = *(const float4*)(Bm + (size_t)br1 * C + nbase + bc);

    float acc[8][8] = {};
    const int tx = t & 15, ty = t >> 4;
    const int ntiles = C >> 4;

    for (int tile = 0; tile < ntiles; tile++) {
        __syncthreads();
        As[ac + 0][ar0] = pa0.x; As[ac + 1][ar0] = pa0.y;
        As[ac + 2][ar0] = pa0.z; As[ac + 3][ar0] = pa0.w;
        As[ac + 0][ar1] = pa1.x; As[ac + 1][ar1] = pa1.y;
        As[ac + 2][ar1] = pa1.z; As[ac + 3][ar1] = pa1.w;
        *(float4*)&Bs[br0][bc] = pb0;
        *(float4*)&Bs[br1][bc] = pb1;
        __syncthreads();

        if (tile + 1 < ntiles) {
            int k0 = (tile + 1) << 4;
            pa0 = *(const float4*)(A + (size_t)(mbase + ar0) * C + k0 + ac);
            pa1 = *(const float4*)(A + (size_t)(mbase + ar1) * C + k0 + ac);
            pb0 = *(const float4*)(Bm + (size_t)(k0 + br0) * C + nbase + bc);
            pb1 = *(const float4*)(Bm + (size_t)(k0 + br1) * C + nbase + bc);
        }

        #pragma unroll
        for (int k = 0; k < 16; k++) {
            float a[8], b[8];
            *(float4*)&a[0] = *(const float4*)&As[k][ty * 4];
            *(float4*)&a[4] = *(const float4*)&As[k][64 + ty * 4];
            *(float4*)&b[0] = *(const float4*)&Bs[k][tx * 4];
            *(float4*)&b[4] = *(const float4*)&Bs[k][64 + tx * 4];
            #pragma unroll
            for (int i = 0; i < 8; i++)
                #pragma unroll
                for (int j = 0; j < 8; j++)
                    acc[i][j] += a[i] * b[j];
        }
    }

    // transposed epilogue: hT[b][channel][token]
    #pragma unroll
    for (int j = 0; j < 8; j++) {
        int gc = nbase + (j < 4 ? tx * 4 + j : 64 + tx * 4 + (j - 4));
        float bi = bias[gc];
        int gr0 = mbase + ty * 4;
        int bb0 = gr0 >> 12, n0 = gr0 & 4095;
        float4 v0;
        v0.x = acc[0][j] + bi; v0.y = acc[1][j] + bi;
        v0.z = acc[2][j] + bi; v0.w = acc[3][j] + bi;
        *(float4*)(g_hT + ((size_t)bb0 * C + gc) * Nq + n0) = v0;
        int gr1 = mbase + 64 + ty * 4;
        int bb1 = gr1 >> 12, n1 = gr1 & 4095;
        float4 v1;
        v1.x = acc[4][j] + bi; v1.y = acc[5][j] + bi;
        v1.z = acc[6][j] + bi; v1.w = acc[7][j] + bi;
        *(float4*)(g_hT + ((size_t)bb1 * C + gc) * Nq + n1) = v1;
    }
}

// ===========================================================================
// Kernel 3: scores  s[b,q,n] = sum_k g[b,q,k] * f[b,n,k]
// 3x tf32 mma.sync (hi/lo split) -> fp32-grade logits.
// CTA 128x128, 8 warps (2x4), warp tile 64x32.
// ===========================================================================
__global__ __launch_bounds__(256)
void score_kernel() {
    __shared__ float Gs[128][36];
    __shared__ float Fs[128][36];
    const int t = threadIdx.x;
    const int lane = t & 31, wid = t >> 5;
    const int wm = wid >> 2, wn = wid & 3;
    const int mbase = blockIdx.y * 128, nbase = blockIdx.x * 128;
    const size_t zoff = (size_t)blockIdx.z * Nq * CK;

    #pragma unroll
    for (int i = 0; i < 4; i++) {
        int idx = t + i * 256;
        int r = idx >> 3, c4 = (idx & 7) * 4;
        *(float4*)&Gs[r][c4] = *(const float4*)(g_g + zoff + (size_t)(mbase + r) * CK + c4);
        *(float4*)&Fs[r][c4] = *(const float4*)(g_f + zoff + (size_t)(nbase + r) * CK + c4);
    }
    __syncthreads();

    float acc[4][4][4] = {};
    #pragma unroll
    for (int ks = 0; ks < 4; ks++) {
        const int cc = ks * 8 + (lane & 3);
        uint32_t ah[4][4], al[4][4];
        #pragma unroll
        for (int mt = 0; mt < 4; mt++) {
            int r0 = wm * 64 + mt * 16 + (lane >> 2);
            float v0 = Gs[r0][cc],     v1 = Gs[r0 + 8][cc];
            float v2 = Gs[r0][cc + 4], v3 = Gs[r0 + 8][cc + 4];
            ah[mt][0] = f2tf32(v0); al[mt][0] = f2tf32(v0 - __uint_as_float(ah[mt][0]));
            ah[mt][1] = f2tf32(v1); al[mt][1] = f2tf32(v1 - __uint_as_float(ah[mt][1]));
            ah[mt][2] = f2tf32(v2); al[mt][2] = f2tf32(v2 - __uint_as_float(ah[mt][2]));
            ah[mt][3] = f2tf32(v3); al[mt][3] = f2tf32(v3 - __uint_as_float(ah[mt][3]));
        }
        #pragma unroll
        for (int nt = 0; nt < 4; nt++) {
            int rn = wn * 32 + nt * 8 + (lane >> 2);
            float w0 = Fs[rn][cc], w1 = Fs[rn][cc + 4];
            uint32_t bh[2], bl[2];
            bh[0] = f2tf32(w0); bl[0] = f2tf32(w0 - __uint_as_float(bh[0]));
            bh[1] = f2tf32(w1); bl[1] = f2tf32(w1 - __uint_as_float(bh[1]));
            #pragma unroll
            for (int mt = 0; mt < 4; mt++) {
                mma_tf32(acc[mt][nt], ah[mt], bh);
                mma_tf32(acc[mt][nt], ah[mt], bl);
                mma_tf32(acc[mt][nt], al[mt], bh);
            }
        }
    }

    float* sout = g_s + (size_t)blockIdx.z * Nq * Nq;
    #pragma unroll
    for (int mt = 0; mt < 4; mt++) {
        int r0 = mbase + wm * 64 + mt * 16 + (lane >> 2);
        #pragma unroll
        for (int nt = 0; nt < 4; nt++) {
            int col = nbase + wn * 32 + nt * 8 + 2 * (lane & 3);
            float2 o0; o0.x = acc[mt][nt][0]; o0.y = acc[mt][nt][1];
            *(float2*)(sout + (size_t)r0 * Nq + col) = o0;
            float2 o1; o1.x = acc[mt][nt][2]; o1.y = acc[mt][nt][3];
            *(float2*)(sout + (size_t)(r0 + 8) * Nq + col) = o1;
        }
    }
}

// ===========================================================================
// Kernel 4: fused exp-softmax + PV + residual.
//   p = exp(s) (no max sub; |s|max ~ 34 << 88), Z accumulated in-kernel.
//   o[q,c] = (sum_n p*h) / Z ;  y = gamma*o + x
//   CTA: M=128 q x N=256 c (full C), K = all 4096 n in chunks of 32.
//   A (P->exp) path: LDG prefetch (2 deep) -> expf -> STS, 3 smem stages.
//   B (hT) path: cp.async, 4 smem stages.
//   8 warps (2m x 4n), warp tile 64x64 -> acc[4][8][4].
// ===========================================================================
constexpr int PV_AROW = 36;                        // 32 + 4 pad
constexpr int PV_AST  = 128 * PV_AROW;             // floats per A stage
constexpr int PV_BST  = 256 * PV_AROW;             // floats per B stage
constexpr int PV_SMEM = (3 * PV_AST + 4 * PV_BST + 128) * 4;   // 203,776 B
constexpr int NCH = Nq / 32;                       // 128

__global__ __launch_bounds__(256, 1)
void pv_kernel(const float* __restrict__ gamma_p,
               const float* __restrict__ x, float* __restrict__ y) {
    extern __shared__ float sm[];
    float* Abuf = sm;
    float* Bbuf = sm + 3 * PV_AST;
    float* zsm  = sm + 3 * PV_AST + 4 * PV_BST;

    const int t = threadIdx.x;
    const int lane = t & 31, wid = t >> 5;
    const int wm = wid >> 2, wn = wid & 3;         // 2(M) x 4(N)
    const int qbase = blockIdx.x * 128;
    const int b = blockIdx.y;
    const float* Pm  = g_s  + (size_t)b * Nq * Nq;
    const float* hTb = g_hT + (size_t)b * C * Nq;

    if (t < 128) zsm[t] = 0.f;

    const int tr  = t >> 3;          // 0..31
    const int tc4 = (t & 7) * 4;     // 0..28

    float4 va[4], vb[4];
    float zp[4] = {0.f, 0.f, 0.f, 0.f};

    auto ldgA = [&](int chunk, float4* v) {
        const float* base = Pm + (size_t)(qbase + tr) * Nq + chunk * 32 + tc4;
        #pragma unroll
        for (int i = 0; i < 4; i++)
            v[i] = *(const float4*)(base + (size_t)(32 * i) * Nq);
    };
    auto expSts = [&](int chunk, const float4* v) {
        float* Ad = Abuf + (chunk % 3) * PV_AST;
        #pragma unroll
        for (int i = 0; i < 4; i++) {
            float4 p;
            p.x = __expf(v[i].x); p.y = __expf(v[i].y);
            p.z = __expf(v[i].z); p.w = __expf(v[i].w);
            zp[i] += (p.x + p.y) + (p.z + p.w);
            *(float4*)(Ad + (tr + 32 * i) * PV_AROW + tc4) = p;
        }
    };
    auto cpB = [&](int chunk) {
        float* Bd = Bbuf + (chunk & 3) * PV_BST;
        #pragma unroll
        for (int i = 0; i < 8; i++) {
            int idx = t + i * 256;
            int r = idx >> 3, c4 = (idx & 7) * 4;
            cp16(smem_u32(Bd + r * PV_AROW + c4),
                 hTb + (size_t)r * Nq + chunk * 32 + c4);
        }
        cp_commit();
    };

    // prologue
    cpB(0); cpB(1); cpB(2);
    ldgA(0, va);
    expSts(0, va);
    ldgA(1, va);

    float acc[4][8][4] = {};

    for (int c = 0; c < NCH; c++) {
        if (c + 1 < NCH) expSts(c + 1, va);
        if (c + 2 < NCH) ldgA(c + 2, vb);

        int pend = NCH - 1 - c;
        if (pend > 2)       asm volatile("cp.async.wait_group 2;" ::: "memory");
        else if (pend == 2) asm volatile("cp.async.wait_group 2;" ::: "memory");
        else if (pend == 1) asm volatile("cp.async.wait_group 1;" ::: "memory");
        else                asm volatile("cp.async.wait_group 0;" ::: "memory");
        __syncthreads();

        if (c + 3 < NCH) cpB(c + 3);

        const float* Asb = Abuf + (c % 3) * PV_AST;
        const float* Bsb = Bbuf + (c & 3) * PV_BST;
        #pragma unroll
        for (int ks = 0; ks < 4; ks++) {
            const int cc = ks * 8 + (lane & 3);
            uint32_t af[4][4];
            #pragma unroll
            for (int mt = 0; mt < 4; mt++) {
                int r0 = (wm * 64 + mt * 16 + (lane >> 2)) * PV_AROW;
                af[mt][0] = f2tf32(Asb[r0 + cc]);
                af[mt][1] = f2tf32(Asb[r0 + 8 * PV_AROW + cc]);
                af[mt][2] = f2tf32(Asb[r0 + cc + 4]);
                af[mt][3] = f2tf32(Asb[r0 + 8 * PV_AROW + cc + 4]);
            }
            #pragma unroll
            for (int nt = 0; nt < 8; nt++) {
                int rn = (wn * 64 + nt * 8 + (lane >> 2)) * PV_AROW;
                uint32_t bf[2];
                bf[0] = f2tf32(Bsb[rn + cc]);
                bf[1] = f2tf32(Bsb[rn + cc + 4]);
                #pragma unroll
                for (int mt = 0; mt < 4; mt++)
                    mma_tf32(acc[mt][nt], af[mt], bf);
            }
        }

        #pragma unroll
        for (int i = 0; i < 4; i++) va[i] = vb[i];
    }

    // Z reduction (zsm zero-initialized before first barrier above)
    __syncthreads();
    #pragma unroll
    for (int i = 0; i < 4; i++) atomicAdd(&zsm[tr + 32 * i], zp[i]);
    __syncthreads();

    const float gam = __ldg(gamma_p);
    #pragma unroll
    for (int mt = 0; mt < 4; mt++) {
        int row0 = wm * 64 + mt * 16 + (lane >> 2);
        float sc0 = gam / zsm[row0];
        float sc1 = gam / zsm[row0 + 8];
        #pragma unroll
        for (int nt = 0; nt < 8; nt++) {
            int col = wn * 64 + nt * 8 + 2 * (lane & 3);
            size_t base = ((size_t)b * Nq + qbase + row0) * C + col;
            float2 x0 = *(const float2*)(x + base);
            float2 o0;
            o0.x = sc0 * acc[mt][nt][0] + x0.x;
            o0.y = sc0 * acc[mt][nt][1] + x0.y;
            *(float2*)(y + base) = o0;
            size_t base2 = base + 8 * (size_t)C;
            float2 x1 = *(const float2*)(x + base2);
            float2 o1;
            o1.x = sc1 * acc[mt][nt][2] + x1.x;
            o1.y = sc1 * acc[mt][nt][3] + x1.y;
            *(float2*)(y + base2) = o1;
        }
    }
}

// ===========================================================================
extern "C" void kernel_launch(void* const* d_in, const int* in_sizes, int n_in,
                              void* d_out, int out_size) {
    (void)in_sizes; (void)n_in; (void)out_size;
    const float* x     = (const float*)d_in[0];
    const float* Wf    = (const float*)d_in[1];
    const float* bf    = (const float*)d_in[2];
    const float* Wg    = (const float*)d_in[3];
    const float* bg    = (const float*)d_in[4];
    const float* Wh    = (const float*)d_in[5];
    const float* bh    = (const float*)d_in[6];
    const float* gamma = (const float*)d_in[7];
    float* y = (float*)d_out;

    cudaFuncSetAttribute(pv_kernel, cudaFuncAttributeMaxDynamicSharedMemorySize, PV_SMEM);

    fg_kernel<<<(Bb * Nq) / 32, 256>>>(x, Wf, bf, Wg, bg);
    gemmh_kernel<<<dim3(2, (Bb * Nq) / 128), 256>>>(x, Wh, bh);
    score_kernel<<<dim3(Nq / 128, Nq / 128, Bb), 256>>>();
    pv_kernel<<<dim3(Nq / 128, Bb), 256, PV_SMEM>>>(gamma, x, y);
}

// round 5
// speedup vs baseline: 2.2444x; 1.0324x over previous
#include <cuda_runtime.h>
#include <cstdint>

// Problem dims (fixed by dataset)
constexpr int Bb = 4;      // batch
constexpr int Nq = 4096;   // H*W
constexpr int C  = 256;    // channels
constexpr int CK = 32;     // key/query channels

// Scratch in __device__ globals (allocation-free rule)
__device__ float g_f[(size_t)Bb * Nq * CK];              // keys
__device__ float g_g[(size_t)Bb * Nq * CK];              // queries
__device__ float g_hT[(size_t)Bb * C * Nq];              // values, transposed, tf32-pre-rounded
__device__ float g_s[(size_t)Bb * Nq * Nq];              // raw scores (256 MB)

__device__ __forceinline__ uint32_t smem_u32(const void* p) {
    return (uint32_t)__cvta_generic_to_shared(p);
}
__device__ __forceinline__ void cp16(uint32_t s, const void* g) {
    asm volatile("cp.async.cg.shared.global [%0], [%1], 16;" :: "r"(s), "l"(g));
}
__device__ __forceinline__ void cp_commit() {
    asm volatile("cp.async.commit_group;" ::: "memory");
}
__device__ __forceinline__ uint32_t f2tf32(float f) {
    uint32_t u;
    asm("cvt.rna.tf32.f32 %0, %1;" : "=r"(u) : "f"(f));
    return u;
}
__device__ __forceinline__ void mma_tf32(float* d, const uint32_t* a, const uint32_t* bfr) {
    asm volatile(
        "mma.sync.aligned.m16n8k8.row.col.f32.tf32.tf32.f32 "
        "{%0,%1,%2,%3}, {%4,%5,%6,%7}, {%8,%9}, {%0,%1,%2,%3};"
        : "+f"(d[0]), "+f"(d[1]), "+f"(d[2]), "+f"(d[3])
        : "r"(a[0]), "r"(a[1]), "r"(a[2]), "r"(a[3]), "r"(bfr[0]), "r"(bfr[1]));
}

// ===========================================================================
// Kernel 1: f = x@Wf + bf, g = x@Wg + bg
// ===========================================================================
__global__ void fg_kernel(const float* __restrict__ x,
                          const float* __restrict__ Wf, const float* __restrict__ bfv,
                          const float* __restrict__ Wg, const float* __restrict__ bgv) {
    __shared__ float xs[32][260];
    const int t = threadIdx.x;
    const int rowbase = blockIdx.x * 32;

    for (int i = t; i < 32 * (C / 4); i += 256) {
        int r = i / (C / 4), c4 = i % (C / 4);
        float4 v = *(const float4*)(x + (size_t)(rowbase + r) * C + c4 * 4);
        *(float4*)&xs[r][c4 * 4] = v;
    }
    __syncthreads();

    const int c = t & 31, rg = t >> 5;
    float af[4] = {0.f, 0.f, 0.f, 0.f};
    float ag[4] = {0.f, 0.f, 0.f, 0.f};
    #pragma unroll 4
    for (int k = 0; k < C; k++) {
        float wf = Wf[k * CK + c];
        float wg = Wg[k * CK + c];
        #pragma unroll
        for (int r4 = 0; r4 < 4; r4++) {
            float xv = xs[rg + r4 * 8][k];
            af[r4] += xv * wf;
            ag[r4] += xv * wg;
        }
    }
    #pragma unroll
    for (int r4 = 0; r4 < 4; r4++) {
        size_t o = (size_t)(rowbase + rg + r4 * 8) * CK + c;
        g_f[o] = af[r4] + bfv[c];
        g_g[o] = ag[r4] + bgv[c];
    }
}

// ===========================================================================
// Kernel 2: h projection -> TRANSPOSED + tf32-pre-rounded  g_hT[b][c][n]
// ===========================================================================
__global__ __launch_bounds__(256, 2)
void gemmh_kernel(const float* __restrict__ A, const float* __restrict__ Bm,
                  const float* __restrict__ bias) {
    __shared__ float As[16][128];
    __shared__ float Bs[16][128];

    const int t = threadIdx.x;
    const int mbase = blockIdx.y * 128, nbase = blockIdx.x * 128;

    const int ar0 = t >> 2, ar1 = (t >> 2) + 64;
    const int ac  = (t & 3) * 4;
    const int br0 = t >> 5, br1 = (t >> 5) + 8;
    const int bc  = (t & 31) * 4;

    float4 pa0, pa1, pb0, pb1;
    pa0 = *(const float4*)(A + (size_t)(mbase + ar0) * C + ac);
    pa1 = *(const float4*)(A + (size_t)(mbase + ar1) * C + ac);
    pb0 = *(const float4*)(Bm + (size_t)br0 * C + nbase + bc);
    pb1 = *(const float4*)(Bm + (size_t)br1 * C + nbase + bc);

    float acc[8][8] = {};
    const int tx = t & 15, ty = t >> 4;
    const int ntiles = C >> 4;

    for (int tile = 0; tile < ntiles; tile++) {
        __syncthreads();
        As[ac + 0][ar0] = pa0.x; As[ac + 1][ar0] = pa0.y;
        As[ac + 2][ar0] = pa0.z; As[ac + 3][ar0] = pa0.w;
        As[ac + 0][ar1] = pa1.x; As[ac + 1][ar1] = pa1.y;
        As[ac + 2][ar1] = pa1.z; As[ac + 3][ar1] = pa1.w;
        *(float4*)&Bs[br0][bc] = pb0;
        *(float4*)&Bs[br1][bc] = pb1;
        __syncthreads();

        if (tile + 1 < ntiles) {
            int k0 = (tile + 1) << 4;
            pa0 = *(const float4*)(A + (size_t)(mbase + ar0) * C + k0 + ac);
            pa1 = *(const float4*)(A + (size_t)(mbase + ar1) * C + k0 + ac);
            pb0 = *(const float4*)(Bm + (size_t)(k0 + br0) * C + nbase + bc);
            pb1 = *(const float4*)(Bm + (size_t)(k0 + br1) * C + nbase + bc);
        }

        #pragma unroll
        for (int k = 0; k < 16; k++) {
            float a[8], b[8];
            *(float4*)&a[0] = *(const float4*)&As[k][ty * 4];
            *(float4*)&a[4] = *(const float4*)&As[k][64 + ty * 4];
            *(float4*)&b[0] = *(const float4*)&Bs[k][tx * 4];
            *(float4*)&b[4] = *(const float4*)&Bs[k][64 + tx * 4];
            #pragma unroll
            for (int i = 0; i < 8; i++)
                #pragma unroll
                for (int j = 0; j < 8; j++)
                    acc[i][j] += a[i] * b[j];
        }
    }

    // transposed epilogue, tf32 pre-rounding (pv's B operand needs no cvt)
    #pragma unroll
    for (int j = 0; j < 8; j++) {
        int gc = nbase + (j < 4 ? tx * 4 + j : 64 + tx * 4 + (j - 4));
        float bi = bias[gc];
        int gr0 = mbase + ty * 4;
        int bb0 = gr0 >> 12, n0 = gr0 & 4095;
        float4 v0;
        v0.x = __uint_as_float(f2tf32(acc[0][j] + bi));
        v0.y = __uint_as_float(f2tf32(acc[1][j] + bi));
        v0.z = __uint_as_float(f2tf32(acc[2][j] + bi));
        v0.w = __uint_as_float(f2tf32(acc[3][j] + bi));
        *(float4*)(g_hT + ((size_t)bb0 * C + gc) * Nq + n0) = v0;
        int gr1 = mbase + 64 + ty * 4;
        int bb1 = gr1 >> 12, n1 = gr1 & 4095;
        float4 v1;
        v1.x = __uint_as_float(f2tf32(acc[4][j] + bi));
        v1.y = __uint_as_float(f2tf32(acc[5][j] + bi));
        v1.z = __uint_as_float(f2tf32(acc[6][j] + bi));
        v1.w = __uint_as_float(f2tf32(acc[7][j] + bi));
        *(float4*)(g_hT + ((size_t)bb1 * C + gc) * Nq + n1) = v1;
    }
}

// ===========================================================================
// Kernel 3: scores via 3x tf32 mma.sync (hi/lo split) -> fp32-grade logits.
// ===========================================================================
__global__ __launch_bounds__(256)
void score_kernel() {
    __shared__ float Gs[128][36];
    __shared__ float Fs[128][36];
    const int t = threadIdx.x;
    const int lane = t & 31, wid = t >> 5;
    const int wm = wid >> 2, wn = wid & 3;
    const int mbase = blockIdx.y * 128, nbase = blockIdx.x * 128;
    const size_t zoff = (size_t)blockIdx.z * Nq * CK;

    #pragma unroll
    for (int i = 0; i < 4; i++) {
        int idx = t + i * 256;
        int r = idx >> 3, c4 = (idx & 7) * 4;
        *(float4*)&Gs[r][c4] = *(const float4*)(g_g + zoff + (size_t)(mbase + r) * CK + c4);
        *(float4*)&Fs[r][c4] = *(const float4*)(g_f + zoff + (size_t)(nbase + r) * CK + c4);
    }
    __syncthreads();

    float acc[4][4][4] = {};
    #pragma unroll
    for (int ks = 0; ks < 4; ks++) {
        const int cc = ks * 8 + (lane & 3);
        uint32_t ah[4][4], al[4][4];
        #pragma unroll
        for (int mt = 0; mt < 4; mt++) {
            int r0 = wm * 64 + mt * 16 + (lane >> 2);
            float v0 = Gs[r0][cc],     v1 = Gs[r0 + 8][cc];
            float v2 = Gs[r0][cc + 4], v3 = Gs[r0 + 8][cc + 4];
            ah[mt][0] = f2tf32(v0); al[mt][0] = f2tf32(v0 - __uint_as_float(ah[mt][0]));
            ah[mt][1] = f2tf32(v1); al[mt][1] = f2tf32(v1 - __uint_as_float(ah[mt][1]));
            ah[mt][2] = f2tf32(v2); al[mt][2] = f2tf32(v2 - __uint_as_float(ah[mt][2]));
            ah[mt][3] = f2tf32(v3); al[mt][3] = f2tf32(v3 - __uint_as_float(ah[mt][3]));
        }
        #pragma unroll
        for (int nt = 0; nt < 4; nt++) {
            int rn = wn * 32 + nt * 8 + (lane >> 2);
            float w0 = Fs[rn][cc], w1 = Fs[rn][cc + 4];
            uint32_t bh[2], bl[2];
            bh[0] = f2tf32(w0); bl[0] = f2tf32(w0 - __uint_as_float(bh[0]));
            bh[1] = f2tf32(w1); bl[1] = f2tf32(w1 - __uint_as_float(bh[1]));
            #pragma unroll
            for (int mt = 0; mt < 4; mt++) {
                mma_tf32(acc[mt][nt], ah[mt], bh);
                mma_tf32(acc[mt][nt], ah[mt], bl);
                mma_tf32(acc[mt][nt], al[mt], bh);
            }
        }
    }

    float* sout = g_s + (size_t)blockIdx.z * Nq * Nq;
    #pragma unroll
    for (int mt = 0; mt < 4; mt++) {
        int r0 = mbase + wm * 64 + mt * 16 + (lane >> 2);
        #pragma unroll
        for (int nt = 0; nt < 4; nt++) {
            int col = nbase + wn * 32 + nt * 8 + 2 * (lane & 3);
            float2 o0; o0.x = acc[mt][nt][0]; o0.y = acc[mt][nt][1];
            *(float2*)(sout + (size_t)r0 * Nq + col) = o0;
            float2 o1; o1.x = acc[mt][nt][2]; o1.y = acc[mt][nt][3];
            *(float2*)(sout + (size_t)(r0 + 8) * Nq + col) = o1;
        }
    }
}

// ===========================================================================
// Kernel 4: fused exp-softmax + PV + residual.  512 threads, 16 warps (2m x 8n).
//   All smem data pre-rounded to tf32 by producers -> MMA loop is LDS+HMMA only.
// ===========================================================================
constexpr int PV_AROW = 36;                        // 32 + 4 pad
constexpr int PV_AST  = 128 * PV_AROW;
constexpr int PV_BST  = 256 * PV_AROW;
constexpr int PV_SMEM = (3 * PV_AST + 4 * PV_BST + 128) * 4;   // 203,776 B
constexpr int NCH = Nq / 32;                       // 128

__global__ __launch_bounds__(512, 1)
void pv_kernel(const float* __restrict__ gamma_p,
               const float* __restrict__ x, float* __restrict__ y) {
    extern __shared__ float sm[];
    float* Abuf = sm;
    float* Bbuf = sm + 3 * PV_AST;
    float* zsm  = sm + 3 * PV_AST + 4 * PV_BST;

    const int t = threadIdx.x;
    const int lane = t & 31, wid = t >> 5;
    const int wm = wid >> 3, wn = wid & 7;         // 2(M) x 8(N)
    const int qbase = blockIdx.x * 128;
    const int b = blockIdx.y;
    const float* Pm  = g_s  + (size_t)b * Nq * Nq;
    const float* hTb = g_hT + (size_t)b * C * Nq;

    if (t < 128) zsm[t] = 0.f;

    const int tr  = t >> 3;          // 0..63
    const int tc4 = (t & 7) * 4;

    float4 va[2], vb[2];
    float zp[2] = {0.f, 0.f};

    auto ldgA = [&](int chunk, float4* v) {
        const float* base = Pm + (size_t)(qbase + tr) * Nq + chunk * 32 + tc4;
        v[0] = *(const float4*)(base);
        v[1] = *(const float4*)(base + (size_t)64 * Nq);
    };
    auto expSts = [&](int chunk, const float4* v) {
        float* Ad = Abuf + (chunk % 3) * PV_AST;
        #pragma unroll
        for (int i = 0; i < 2; i++) {
            float4 p;
            p.x = __uint_as_float(f2tf32(__expf(v[i].x)));
            p.y = __uint_as_float(f2tf32(__expf(v[i].y)));
            p.z = __uint_as_float(f2tf32(__expf(v[i].z)));
            p.w = __uint_as_float(f2tf32(__expf(v[i].w)));
            zp[i] += (p.x + p.y) + (p.z + p.w);
            *(float4*)(Ad + (tr + 64 * i) * PV_AROW + tc4) = p;
        }
    };
    auto cpB = [&](int chunk) {
        float* Bd = Bbuf + (chunk & 3) * PV_BST;
        #pragma unroll
        for (int i = 0; i < 4; i++) {
            int idx = t + i * 512;
            int r = idx >> 3, c4 = (idx & 7) * 4;
            cp16(smem_u32(Bd + r * PV_AROW + c4),
                 hTb + (size_t)r * Nq + chunk * 32 + c4);
        }
        cp_commit();
    };

    // prologue
    cpB(0); cpB(1); cpB(2);
    ldgA(0, va);
    expSts(0, va);
    ldgA(1, va);

    float acc[4][4][4] = {};   // warp tile 64(M) x 32(N)

    for (int c = 0; c < NCH; c++) {
        if (c + 1 < NCH) expSts(c + 1, va);
        if (c + 2 < NCH) ldgA(c + 2, vb);

        int pend = NCH - 1 - c;
        if (pend >= 2)      asm volatile("cp.async.wait_group 2;" ::: "memory");
        else if (pend == 1) asm volatile("cp.async.wait_group 1;" ::: "memory");
        else                asm volatile("cp.async.wait_group 0;" ::: "memory");
        __syncthreads();

        if (c + 3 < NCH) cpB(c + 3);

        const float* Asb = Abuf + (c % 3) * PV_AST;
        const float* Bsb = Bbuf + (c & 3) * PV_BST;
        #pragma unroll
        for (int ks = 0; ks < 4; ks++) {
            const int cc = ks * 8 + (lane & 3);
            uint32_t af[4][4];
            #pragma unroll
            for (int mt = 0; mt < 4; mt++) {
                int r0 = (wm * 64 + mt * 16 + (lane >> 2)) * PV_AROW;
                af[mt][0] = __float_as_uint(Asb[r0 + cc]);
                af[mt][1] = __float_as_uint(Asb[r0 + 8 * PV_AROW + cc]);
                af[mt][2] = __float_as_uint(Asb[r0 + cc + 4]);
                af[mt][3] = __float_as_uint(Asb[r0 + 8 * PV_AROW + cc + 4]);
            }
            #pragma unroll
            for (int nt = 0; nt < 4; nt++) {
                int rn = (wn * 32 + nt * 8 + (lane >> 2)) * PV_AROW;
                uint32_t bf[2];
                bf[0] = __float_as_uint(Bsb[rn + cc]);
                bf[1] = __float_as_uint(Bsb[rn + cc + 4]);
                #pragma unroll
                for (int mt = 0; mt < 4; mt++)
                    mma_tf32(acc[mt][nt], af[mt], bf);
            }
        }

        va[0] = vb[0]; va[1] = vb[1];
    }

    // Z reduction
    __syncthreads();
    atomicAdd(&zsm[tr], zp[0]);
    atomicAdd(&zsm[tr + 64], zp[1]);
    __syncthreads();

    const float gam = __ldg(gamma_p);
    #pragma unroll
    for (int mt = 0; mt < 4; mt++) {
        int row0 = wm * 64 + mt * 16 + (lane >> 2);
        float sc0 = gam / zsm[row0];
        float sc1 = gam / zsm[row0 + 8];
        #pragma unroll
        for (int nt = 0; nt < 4; nt++) {
            int col = wn * 32 + nt * 8 + 2 * (lane & 3);
            size_t base = ((size_t)b * Nq + qbase + row0) * C + col;
            float2 x0 = *(const float2*)(x + base);
            float2 o0;
            o0.x = sc0 * acc[mt][nt][0] + x0.x;
            o0.y = sc0 * acc[mt][nt][1] + x0.y;
            *(float2*)(y + base) = o0;
            size_t base2 = base + 8 * (size_t)C;
            float2 x1 = *(const float2*)(x + base2);
            float2 o1;
            o1.x = sc1 * acc[mt][nt][2] + x1.x;
            o1.y = sc1 * acc[mt][nt][3] + x1.y;
            *(float2*)(y + base2) = o1;
        }
    }
}

// ===========================================================================
extern "C" void kernel_launch(void* const* d_in, const int* in_sizes, int n_in,
                              void* d_out, int out_size) {
    (void)in_sizes; (void)n_in; (void)out_size;
    const float* x     = (const float*)d_in[0];
    const float* Wf    = (const float*)d_in[1];
    const float* bf    = (const float*)d_in[2];
    const float* Wg    = (const float*)d_in[3];
    const float* bg    = (const float*)d_in[4];
    const float* Wh    = (const float*)d_in[5];
    const float* bh    = (const float*)d_in[6];
    const float* gamma = (const float*)d_in[7];
    float* y = (float*)d_out;

    cudaFuncSetAttribute(pv_kernel, cudaFuncAttributeMaxDynamicSharedMemorySize, PV_SMEM);

    fg_kernel<<<(Bb * Nq) / 32, 256>>>(x, Wf, bf, Wg, bg);
    gemmh_kernel<<<dim3(2, (Bb * Nq) / 128), 256>>>(x, Wh, bh);
    score_kernel<<<dim3(Nq / 128, Nq / 128, Bb), 256>>>();
    pv_kernel<<<dim3(Nq / 128, Bb), 512, PV_SMEM>>>(gamma, x, y);
}